// round 3
// baseline (speedup 1.0000x reference)
#include <cuda_runtime.h>
#include <math_constants.h>

#define HH 1024
#define WW 1024
#define NCH 48
#define RSTRIP 16
#define GRP 12          // channels per group (48MB scores + 48MB x reads < 126MB L2)

// Per-channel max of (pre-NMS) scores, as float bits. Scores >= 1e-6 > 0, so
// integer atomicMax on the bit pattern preserves float ordering.
__device__ int g_smax[NCH];

__global__ void init_smax_kernel() {
    if (threadIdx.x < NCH) g_smax[threadIdx.x] = 0;
}

__device__ __forceinline__ void load_xrow(const float* __restrict__ xc, int r, int gc,
                                          int lcm2, int lcm1, int lcp4, int lcp5,
                                          float v[8]) {
    int ry = min(max(r, 0), HH - 1);
    const float* row = xc + ry * WW;
    float4 m = __ldg(reinterpret_cast<const float4*>(row + gc));
    v[0] = __ldg(row + lcm2);
    v[1] = __ldg(row + lcm1);
    v[2] = m.x; v[3] = m.y; v[4] = m.z; v[5] = m.w;
    v[6] = __ldg(row + lcp4);
    v[7] = __ldg(row + lcp5);
}

// Each thread: 4 output columns (gc..gc+3) x RSTRIP output rows, all in registers.
// Score rows/cols needed for NMS halo are recomputed locally (no smem at all).
__global__ __launch_bounds__(256)
void hessian_kernel(const float* __restrict__ x, float* __restrict__ out, int ch0) {
    const int ch = ch0 + blockIdx.y;
    const int y0 = blockIdx.x * RSTRIP;
    const int gc = threadIdx.x * 4;                 // output cols gc..gc+3
    const float* __restrict__ xc = x + (size_t)ch * (HH * WW);
    float* __restrict__ oc = out + (size_t)ch * (HH * WW);

    const int lcm2 = max(gc - 2, 0), lcm1 = max(gc - 1, 0);
    const int lcp4 = min(gc + 4, WW - 1), lcp5 = min(gc + 5, WW - 1);
    const bool colv0 = (gc > 0);                    // score col gc-1 in image?
    const bool colv5 = (gc + 4 < WW);               // score col gc+4 in image?

    float X[3][8];     // ring of x rows (8 cols: gc-2..gc+5)
    float S[3][6];     // ring of score rows (cols gc-1..gc+4)
    float RM[3][4];    // ring of horizontal 3-max of scores per output col
    float premax = 0.0f;

    load_xrow(xc, y0 - 2, gc, lcm2, lcm1, lcp4, lcp5, X[0]);
    load_xrow(xc, y0 - 1, gc, lcm2, lcm1, lcp4, lcp5, X[1]);

    #pragma unroll
    for (int i = 0; i < RSTRIP + 2; i++) {
        const int sr = y0 - 1 + i;                  // score row being produced
        load_xrow(xc, y0 + i, gc, lcm2, lcm1, lcp4, lcp5, X[(2 + i) % 3]);
        const float* a = X[i % 3];                  // x row sr-1
        const float* b = X[(i + 1) % 3];            // x row sr
        const float* c = X[(i + 2) % 3];            // x row sr+1

        // Vertical column sums (separable kernels)
        float A[8], B[8], C[8];
        #pragma unroll
        for (int k = 0; k < 8; k++) {
            float t = a[k] + c[k];
            A[k] = fmaf(2.0f, b[k], t);             // [1,2,1]  vertical
            B[k] = fmaf(-2.0f, b[k], t);            // [1,-2,1] vertical
            C[k] = a[k] - c[k];                     // [1,0,-1] vertical
        }

        const bool srv = (sr >= 0) && (sr < HH);
        float* s = S[i % 3];
        #pragma unroll
        for (int j = 0; j < 6; j++) {               // score cols gc-1+j
            float gxx = fmaf(-2.0f, A[j + 1], A[j] + A[j + 2]);  // row [1,-2,1]
            float gyy = fmaf(2.0f, B[j + 1], B[j] + B[j + 2]);   // row [1,2,1]
            float gxy = C[j + 2] - C[j];                          // row [-1,0,1]
            float sc = fmaxf(fabsf(fmaf(gxx, gyy, -gxy * gxy)), 1e-6f);
            bool valid = srv && (j == 0 ? colv0 : (j == 5 ? colv5 : true));
            s[j] = valid ? sc : -CUDART_INF_F;
        }

        float* rm = RM[i % 3];
        #pragma unroll
        for (int k = 0; k < 4; k++)
            rm[k] = fmaxf(fmaxf(s[k], s[k + 1]), s[k + 2]);

        if (i >= 2) {
            const int y = y0 + i - 2;
            const float* smid = S[(i + 2) % 3];     // score row y
            const float* rmu = RM[(i + 1) % 3];     // row y-1
            const float* rmm = RM[(i + 2) % 3];     // row y
            const float* rmd = RM[i % 3];           // row y+1
            float4 o;
            float ov[4];
            #pragma unroll
            for (int k = 0; k < 4; k++) {
                float sv = smid[k + 1];
                float p = fmaxf(fmaxf(rmu[k], rmm[k]), rmd[k]);
                ov[k] = (sv == p) ? sv : 0.0f;
                premax = fmaxf(premax, sv);
            }
            o.x = ov[0]; o.y = ov[1]; o.z = ov[2]; o.w = ov[3];
            *reinterpret_cast<float4*>(oc + (size_t)y * WW + gc) = o;
        }
    }

    // Warp-reduce pre-NMS max, one atomic per warp per channel.
    #pragma unroll
    for (int off = 16; off > 0; off >>= 1)
        premax = fmaxf(premax, __shfl_xor_sync(0xffffffff, premax, off));
    if ((threadIdx.x & 31) == 0)
        atomicMax(&g_smax[ch], __float_as_int(premax));
}

__global__ __launch_bounds__(256, 8)
void scale_kernel(float* __restrict__ out, int ch0) {
    const int ch = ch0 + blockIdx.y;
    const float inv = 1.0f / __int_as_float(g_smax[ch]);
    float4* o4 = (float4*)(out + (size_t)ch * (HH * WW));
    int i = blockIdx.x * blockDim.x + threadIdx.x;   // HW/4 float4 elements
    float4 v = o4[i];
    v.x *= inv; v.y *= inv; v.z *= inv; v.w *= inv;
    o4[i] = v;
}

extern "C" void kernel_launch(void* const* d_in, const int* in_sizes, int n_in,
                              void* d_out, int out_size) {
    const float* x = (const float*)d_in[0];
    float* out = (float*)d_out;

    init_smax_kernel<<<1, 64>>>();

    dim3 blk(256);
    dim3 grd(HH / RSTRIP, GRP);
    dim3 sgrd((HH * WW / 4) / 256, GRP);

    // Interleave per channel-group so the scale pass hits scores in L2
    // (group working set: 48MB scores + 48MB x reads < 126MB L2).
    for (int g = 0; g < NCH / GRP; g++) {
        hessian_kernel<<<grd, blk>>>(x, out, g * GRP);
        scale_kernel<<<sgrd, 256>>>(out, g * GRP);
    }
}

// round 4
// speedup vs baseline: 1.0619x; 1.0619x over previous
#include <cuda_runtime.h>
#include <math_constants.h>

#define HH 1024
#define WW 1024
#define NCH 48
#define RSTRIP 16   // rows per block, pass 2
#define RS1 16      // rows per block, pass 1

// Per-channel max of (pre-NMS) scores, as float bits. Scores >= 1e-6 > 0, so
// integer atomicMax on the bit pattern preserves float ordering.
// Init to bits of 1e-6 => the clamp floor is the starting max.
__device__ int g_smax[NCH];

__global__ void init_smax_kernel() {
    if (threadIdx.x < NCH) g_smax[threadIdx.x] = __float_as_int(1e-6f);
}

// ---------------------------------------------------------------------------
// Pass 1: per-channel max of raw scores. No NMS, no stores.
// Each thread: 8 score cols (gc..gc+7); needs x cols gc-1..gc+8 (10 wide).
// Own data = 2 aligned float4; +-1 halo from neighbor lanes via shfl.
// ---------------------------------------------------------------------------
__device__ __forceinline__ void load_row10(const float* __restrict__ row, int gc,
                                           int lane, float u[10]) {
    float4 m0 = *reinterpret_cast<const float4*>(row + gc);
    float4 m1 = *reinterpret_cast<const float4*>(row + gc + 4);
    u[1] = m0.x; u[2] = m0.y; u[3] = m0.z; u[4] = m0.w;
    u[5] = m1.x; u[6] = m1.y; u[7] = m1.z; u[8] = m1.w;
    u[0] = __shfl_up_sync(0xffffffffu, u[8], 1);   // prev lane's gc+7 == our gc-1
    u[9] = __shfl_down_sync(0xffffffffu, u[1], 1); // next lane's gc   == our gc+8
    if (lane == 0)  u[0] = row[max(gc - 1, 0)];
    if (lane == 31) u[9] = row[min(gc + 8, WW - 1)];
}

__global__ __launch_bounds__(128)
void max_kernel(const float* __restrict__ x) {
    const int ch = blockIdx.y;
    const int y0 = blockIdx.x * RS1;
    const int gc = threadIdx.x * 8;
    const int lane = threadIdx.x & 31;
    const float* __restrict__ xc = x + (size_t)ch * (HH * WW);

    float X[3][10];
    load_row10(xc + max(y0 - 1, 0) * WW, gc, lane, X[0]);
    load_row10(xc + y0 * WW, gc, lane, X[1]);

    float m = 0.0f;
    #pragma unroll
    for (int i = 0; i < RS1; i++) {
        const int ry = min(y0 + i + 1, HH - 1);
        load_row10(xc + ry * WW, gc, lane, X[(i + 2) % 3]);
        const float* a = X[i % 3];
        const float* b = X[(i + 1) % 3];
        const float* c = X[(i + 2) % 3];

        float A[10], B[10], C[10];
        #pragma unroll
        for (int k = 0; k < 10; k++) {
            float t = a[k] + c[k];
            A[k] = fmaf(2.0f, b[k], t);
            B[k] = fmaf(-2.0f, b[k], t);
            C[k] = a[k] - c[k];
        }
        #pragma unroll
        for (int j = 0; j < 8; j++) {
            float gxx = fmaf(-2.0f, A[j + 1], A[j] + A[j + 2]);
            float gyy = fmaf(2.0f, B[j + 1], B[j] + B[j + 2]);
            float gxy = C[j + 2] - C[j];
            m = fmaxf(m, fabsf(fmaf(gxx, gyy, -gxy * gxy)));
        }
    }

    #pragma unroll
    for (int off = 16; off > 0; off >>= 1)
        m = fmaxf(m, __shfl_xor_sync(0xffffffffu, m, off));
    if (lane == 0)
        atomicMax(&g_smax[ch], __float_as_int(m));
}

// ---------------------------------------------------------------------------
// Pass 2: scores + NMS + normalization, all in registers.
// Each thread: 4 output cols (gc..gc+3); needs x cols gc-2..gc+5 (8 wide).
// ---------------------------------------------------------------------------
__device__ __forceinline__ void load_row8(const float* __restrict__ row, int gc,
                                          int lane, int lcm2, int lcm1,
                                          int lcp4, int lcp5, float v[8]) {
    float4 m = *reinterpret_cast<const float4*>(row + gc);
    v[2] = m.x; v[3] = m.y; v[4] = m.z; v[5] = m.w;
    v[0] = __shfl_up_sync(0xffffffffu, v[4], 1);   // prev lane's gc+2 == our gc-2
    v[1] = __shfl_up_sync(0xffffffffu, v[5], 1);   // prev lane's gc+3 == our gc-1
    v[6] = __shfl_down_sync(0xffffffffu, v[2], 1); // next lane's gc   == our gc+4
    v[7] = __shfl_down_sync(0xffffffffu, v[3], 1); // next lane's gc+1 == our gc+5
    if (lane == 0)  { v[0] = row[lcm2]; v[1] = row[lcm1]; }
    if (lane == 31) { v[6] = row[lcp4]; v[7] = row[lcp5]; }
}

__global__ __launch_bounds__(256)
void hessian_kernel(const float* __restrict__ x, float* __restrict__ out) {
    const int ch = blockIdx.y;
    const int y0 = blockIdx.x * RSTRIP;
    const int gc = threadIdx.x * 4;
    const int lane = threadIdx.x & 31;
    const float* __restrict__ xc = x + (size_t)ch * (HH * WW);
    float* __restrict__ oc = out + (size_t)ch * (HH * WW);
    const float inv = 1.0f / __int_as_float(g_smax[ch]);

    const int lcm2 = max(gc - 2, 0), lcm1 = max(gc - 1, 0);
    const int lcp4 = min(gc + 4, WW - 1), lcp5 = min(gc + 5, WW - 1);
    const bool colv0 = (gc > 0);
    const bool colv5 = (gc + 4 < WW);

    float X[3][8];   // x rows, cols gc-2..gc+5
    float S[3][6];   // score rows, cols gc-1..gc+4
    float RM[3][4];  // horizontal 3-max per output col

    load_row8(xc + max(y0 - 2, 0) * WW, gc, lane, lcm2, lcm1, lcp4, lcp5, X[0]);
    load_row8(xc + max(y0 - 1, 0) * WW, gc, lane, lcm2, lcm1, lcp4, lcp5, X[1]);

    #pragma unroll
    for (int i = 0; i < RSTRIP + 2; i++) {
        const int sr = y0 - 1 + i;                  // score row being produced
        const int ry = min(max(y0 + i, 0), HH - 1);
        load_row8(xc + ry * WW, gc, lane, lcm2, lcm1, lcp4, lcp5, X[(2 + i) % 3]);
        const float* a = X[i % 3];
        const float* b = X[(i + 1) % 3];
        const float* c = X[(i + 2) % 3];

        float A[8], B[8], C[8];
        #pragma unroll
        for (int k = 0; k < 8; k++) {
            float t = a[k] + c[k];
            A[k] = fmaf(2.0f, b[k], t);
            B[k] = fmaf(-2.0f, b[k], t);
            C[k] = a[k] - c[k];
        }

        const bool srv = (sr >= 0) && (sr < HH);
        float* s = S[i % 3];
        #pragma unroll
        for (int j = 0; j < 6; j++) {               // score cols gc-1+j
            float gxx = fmaf(-2.0f, A[j + 1], A[j] + A[j + 2]);
            float gyy = fmaf(2.0f, B[j + 1], B[j] + B[j + 2]);
            float gxy = C[j + 2] - C[j];
            float sc = fmaxf(fabsf(fmaf(gxx, gyy, -gxy * gxy)), 1e-6f);
            bool valid = srv && (j == 0 ? colv0 : (j == 5 ? colv5 : true));
            s[j] = valid ? sc : -CUDART_INF_F;
        }

        float* rm = RM[i % 3];
        #pragma unroll
        for (int k = 0; k < 4; k++)
            rm[k] = fmaxf(fmaxf(s[k], s[k + 1]), s[k + 2]);

        if (i >= 2) {
            const int y = y0 + i - 2;
            const float* smid = S[(i + 2) % 3];     // score row y
            const float* rmu = RM[(i + 1) % 3];     // row y-1
            const float* rmm = RM[(i + 2) % 3];     // row y
            const float* rmd = RM[i % 3];           // row y+1
            float4 o;
            float ov[4];
            #pragma unroll
            for (int k = 0; k < 4; k++) {
                float sv = smid[k + 1];
                float p = fmaxf(fmaxf(rmu[k], rmm[k]), rmd[k]);
                ov[k] = (sv == p) ? sv * inv : 0.0f;
            }
            o.x = ov[0]; o.y = ov[1]; o.z = ov[2]; o.w = ov[3];
            *reinterpret_cast<float4*>(oc + (size_t)y * WW + gc) = o;
        }
    }
}

extern "C" void kernel_launch(void* const* d_in, const int* in_sizes, int n_in,
                              void* d_out, int out_size) {
    const float* x = (const float*)d_in[0];
    float* out = (float*)d_out;

    init_smax_kernel<<<1, 64>>>();

    dim3 mgrd(HH / RS1, NCH);
    max_kernel<<<mgrd, 128>>>(x);

    dim3 hgrd(HH / RSTRIP, NCH);
    hessian_kernel<<<hgrd, 256>>>(x, out);
}

// round 5
// speedup vs baseline: 1.0637x; 1.0017x over previous
#include <cuda_runtime.h>
#include <math_constants.h>

#define HH 1024
#define WW 1024
#define NCH 48
#define RSTRIP 16
#define SLICES (HH / RSTRIP)   // 64 row-slices per channel

// Per-(channel, row-slice) max of raw |det|. Every slot is written on every
// run by pass 1, so no init kernel and no atomics are needed.
__device__ float g_bmax[NCH * SLICES];

// ---------------------------------------------------------------------------
// Pass 1: per-slice max of raw scores. No NMS, no output stores.
// Each thread: 8 score cols (gc..gc+7); x cols gc-1..gc+8 (2 float4 + 2 scalar).
// ---------------------------------------------------------------------------
__device__ __forceinline__ void ldrow10(const float* __restrict__ row, int gc,
                                        int lcm1, int lcp8, float u[10]) {
    float4 m0 = *reinterpret_cast<const float4*>(row + gc);
    float4 m1 = *reinterpret_cast<const float4*>(row + gc + 4);
    u[0] = row[lcm1];
    u[1] = m0.x; u[2] = m0.y; u[3] = m0.z; u[4] = m0.w;
    u[5] = m1.x; u[6] = m1.y; u[7] = m1.z; u[8] = m1.w;
    u[9] = row[lcp8];
}

__global__ __launch_bounds__(128)
void max_kernel(const float* __restrict__ x) {
    __shared__ float wmax[4];
    const int ch = blockIdx.y;
    const int y0 = blockIdx.x * RSTRIP;
    const int gc = threadIdx.x * 8;
    const float* __restrict__ xc = x + (size_t)ch * (HH * WW);
    const int lcm1 = max(gc - 1, 0), lcp8 = min(gc + 8, WW - 1);

    float X[3][10];
    ldrow10(xc + max(y0 - 1, 0) * WW, gc, lcm1, lcp8, X[0]);
    ldrow10(xc + y0 * WW, gc, lcm1, lcp8, X[1]);

    float m = 0.0f;
    #pragma unroll
    for (int i = 0; i < RSTRIP; i++) {
        const int ry = min(y0 + i + 1, HH - 1);
        ldrow10(xc + ry * WW, gc, lcm1, lcp8, X[(i + 2) % 3]);
        const float* a = X[i % 3];
        const float* b = X[(i + 1) % 3];
        const float* c = X[(i + 2) % 3];

        float A[10], B[10], C[10];
        #pragma unroll
        for (int k = 0; k < 10; k++) {
            float t = a[k] + c[k];
            A[k] = fmaf(2.0f, b[k], t);
            B[k] = fmaf(-2.0f, b[k], t);
            C[k] = a[k] - c[k];
        }
        #pragma unroll
        for (int j = 0; j < 8; j++) {
            float gxx = fmaf(-2.0f, A[j + 1], A[j] + A[j + 2]);
            float gyy = fmaf(2.0f, B[j + 1], B[j] + B[j + 2]);
            float gxy = C[j + 2] - C[j];
            m = fmaxf(m, fabsf(fmaf(gxx, gyy, -gxy * gxy)));
        }
    }

    #pragma unroll
    for (int off = 16; off > 0; off >>= 1)
        m = fmaxf(m, __shfl_xor_sync(0xffffffffu, m, off));
    const int lane = threadIdx.x & 31;
    if (lane == 0) wmax[threadIdx.x >> 5] = m;
    __syncthreads();
    if (threadIdx.x == 0) {
        m = fmaxf(fmaxf(wmax[0], wmax[1]), fmaxf(wmax[2], wmax[3]));
        g_bmax[ch * SLICES + blockIdx.x] = m;
    }
}

// ---------------------------------------------------------------------------
// Pass 2: scores + separable NMS + normalization, registers only.
// Each thread: 4 output cols (gc..gc+3); x cols gc-2..gc+5 (1 float4 + 4 scalar).
// ---------------------------------------------------------------------------
__device__ __forceinline__ void ldrow8(const float* __restrict__ row, int gc,
                                       int lcm2, int lcm1, int lcp4, int lcp5,
                                       float v[8]) {
    float4 m = *reinterpret_cast<const float4*>(row + gc);
    v[0] = row[lcm2]; v[1] = row[lcm1];
    v[2] = m.x; v[3] = m.y; v[4] = m.z; v[5] = m.w;
    v[6] = row[lcp4]; v[7] = row[lcp5];
}

__global__ __launch_bounds__(256, 5)
void hessian_kernel(const float* __restrict__ x, float* __restrict__ out) {
    __shared__ float redsm[2];
    const int ch = blockIdx.y;
    const int y0 = blockIdx.x * RSTRIP;
    const int gc = threadIdx.x * 4;
    const float* __restrict__ xc = x + (size_t)ch * (HH * WW);
    float* __restrict__ oc = out + (size_t)ch * (HH * WW);

    // Reduce the 64 per-slice maxima for this channel (L2-hit loads).
    if (threadIdx.x < SLICES) {
        float v = g_bmax[ch * SLICES + threadIdx.x];
        #pragma unroll
        for (int off = 16; off > 0; off >>= 1)
            v = fmaxf(v, __shfl_xor_sync(0xffffffffu, v, off));
        if ((threadIdx.x & 31) == 0) redsm[threadIdx.x >> 5] = v;
    }
    __syncthreads();
    const float inv = 1.0f / fmaxf(fmaxf(redsm[0], redsm[1]), 1e-6f);

    const int lcm2 = max(gc - 2, 0), lcm1 = max(gc - 1, 0);
    const int lcp4 = min(gc + 4, WW - 1), lcp5 = min(gc + 5, WW - 1);
    const bool colv0 = (gc > 0);
    const bool colv5 = (gc + 4 < WW);

    float X[3][8];   // x rows, cols gc-2..gc+5
    float S[3][6];   // score rows, cols gc-1..gc+4

    ldrow8(xc + max(y0 - 2, 0) * WW, gc, lcm2, lcm1, lcp4, lcp5, X[0]);
    ldrow8(xc + max(y0 - 1, 0) * WW, gc, lcm2, lcm1, lcp4, lcp5, X[1]);

    #pragma unroll
    for (int i = 0; i < RSTRIP + 2; i++) {
        const int sr = y0 - 1 + i;                  // score row produced this iter
        const int ry = min(y0 + i, HH - 1);
        ldrow8(xc + ry * WW, gc, lcm2, lcm1, lcp4, lcp5, X[(2 + i) % 3]);
        const float* a = X[i % 3];
        const float* b = X[(i + 1) % 3];
        const float* c = X[(i + 2) % 3];

        float A[8], B[8], C[8];
        #pragma unroll
        for (int k = 0; k < 8; k++) {
            float t = a[k] + c[k];
            A[k] = fmaf(2.0f, b[k], t);
            B[k] = fmaf(-2.0f, b[k], t);
            C[k] = a[k] - c[k];
        }

        const bool srv = (sr >= 0) && (sr < HH);
        float* s = S[i % 3];
        #pragma unroll
        for (int j = 0; j < 6; j++) {               // score cols gc-1+j
            float gxx = fmaf(-2.0f, A[j + 1], A[j] + A[j + 2]);
            float gyy = fmaf(2.0f, B[j + 1], B[j] + B[j + 2]);
            float gxy = C[j + 2] - C[j];
            float sc = fmaxf(fabsf(fmaf(gxx, gyy, -gxy * gxy)), 1e-6f);
            bool valid = srv && (j == 0 ? colv0 : (j == 5 ? colv5 : true));
            s[j] = valid ? sc : -CUDART_INF_F;
        }

        if (i >= 2) {
            const int y = y0 + i - 2;
            // The three S-ring rows are exactly score rows y-1, y, y+1.
            float cm[6];
            #pragma unroll
            for (int k = 0; k < 6; k++)
                cm[k] = fmaxf(fmaxf(S[0][k], S[1][k]), S[2][k]);
            const float* smid = S[(i + 2) % 3];     // score row y
            float ov[4];
            #pragma unroll
            for (int k = 0; k < 4; k++) {
                float p = fmaxf(fmaxf(cm[k], cm[k + 1]), cm[k + 2]);
                float sv = smid[k + 1];
                ov[k] = (sv == p) ? sv * inv : 0.0f;
            }
            float4 o; o.x = ov[0]; o.y = ov[1]; o.z = ov[2]; o.w = ov[3];
            *reinterpret_cast<float4*>(oc + (size_t)y * WW + gc) = o;
        }
    }
}

extern "C" void kernel_launch(void* const* d_in, const int* in_sizes, int n_in,
                              void* d_out, int out_size) {
    const float* x = (const float*)d_in[0];
    float* out = (float*)d_out;

    dim3 mgrd(SLICES, NCH);
    max_kernel<<<mgrd, 128>>>(x);

    dim3 hgrd(HH / RSTRIP, NCH);
    hessian_kernel<<<hgrd, 256>>>(x, out);
}